// round 17
// baseline (speedup 1.0000x reference)
#include <cuda_runtime.h>

#define NN 3072u
#define NPAIRS (NN * NN)                 // 9,437,184
#define TOTAL_QUADS (NPAIRS * 4u)        // 37,748,736 float4 slots
#define UNROLL 8u
#define TPB 256u
#define SPAN (TOTAL_QUADS / UNROLL)      // 4,718,592 quads per partition
#define PSTRIDE (SPAN / 4u)              // 1,179,648 pairs per partition step
#define ISTRIDE (PSTRIDE / NN)           // 384 rows per partition step (exact)

// jax x64 disabled: the "int64" inputs are actually int32.
__device__ __forceinline__ int node_code(int c, int b, int idx) {
    bool ok = (c != 24) && (c != 25) && (c != 26);
    return ok ? b : (-1 - idx);
}

// Single fused kernel: 604MB write stream with the pair predicate resolved
// inline. Partition algebra (PSTRIDE = 384*NN exactly): across a thread's 8
// partitions q and j are constant (one z2 load, one j-code), i strides by
// 384 and is warp-uniform (broadcast cls/batch loads, L1-hot, 24KB total).
// seg is ONLY read for code-matching pairs (~6%, clustered in diagonal
// batch blocks -> a warp's matching lanes read one contiguous 32B sector):
// ~2.4MB of reads against 604MB of writes, so no stream-turnaround cost.
// UNROLL 8 amortizes the per-thread setup (division, j-code, z2 load) over
// twice the stores; body is lean enough to stay within 32 regs.
__global__ void __launch_bounds__(TPB, 8)
fused_pair_kernel(const float4* __restrict__ z1,   // [N][4] float4
                  const float4* __restrict__ z2,   // [N][4] float4
                  const float*  __restrict__ seg,  // [N*N]
                  const int*    __restrict__ cls,
                  const int*    __restrict__ batch,
                  float4*       __restrict__ out)  // [N*N*4]
{
    unsigned base = blockIdx.x * TPB + threadIdx.x;   // < SPAN
    unsigned pr0  = base >> 2;
    unsigned q    = base & 3u;
    unsigned i0   = pr0 / NN;
    unsigned j    = pr0 - i0 * NN;

    int code_j = node_code(__ldg(cls + j), __ldg(batch + j), (int)j);

    float4 b    = z2[j * 4u + q];            // shared by all 8 partitions
    float4 vdef = make_float4(q == 0u ? 1.0f : 0.0f, 0.0f, 0.0f, 0.0f);

#pragma unroll
    for (unsigned k = 0; k < UNROLL; k++) {
        unsigned i = i0 + k * ISTRIDE;       // warp-uniform row
        int code_i = node_code(__ldg(cls + i), __ldg(batch + i), (int)i);

        float4 v = vdef;
        if ((code_i == code_j) && (i != j)) {
            // seg + eye: diagonal excluded above; read seg only when the
            // batch/class gate passes (~6% of pairs).
            float s = __ldg(seg + i * NN + j);
            if (s == 0.0f) {
                float4 a = z1[i * 4u + q];   // cache-hot (96KB)
                v = make_float4(a.x * b.x, a.y * b.y, a.z * b.z, a.w * b.w);
            }
        }
        __stcs(out + base + k * SPAN, v);    // 604MB pure write stream
    }
}

extern "C" void kernel_launch(void* const* d_in, const int* in_sizes, int n_in,
                              void* d_out, int out_size) {
    const float4* z1    = (const float4*)d_in[0];
    const float4* z2    = (const float4*)d_in[1];
    const float*  seg   = (const float*)d_in[2];
    const int*    cls   = (const int*)d_in[3];
    const int*    batch = (const int*)d_in[4];
    float4*       out   = (float4*)d_out;

    fused_pair_kernel<<<SPAN / TPB, TPB>>>(z1, z2, seg, cls, batch, out);
}